// round 11
// baseline (speedup 1.0000x reference)
#include <cuda_runtime.h>

// Problem constants (fixed by the reference):
//   image 1000x1000, patch 5x5 -> 200x200 = 40000 patches
//   coefficients [40000, 3, 10, 2], bias [40000, 3]
//   out [3, 1000000]
#define IMG_W           1000
#define NUM_PIX         1000000
#define PATCH           5
#define PATCHES_PER_ROW 200
#define COEF_PER_PATCH  60          // 3*10*2
#define NTHREADS        256         // 8 warps x 5 patches = 40 patches per block
#define GRID            1000

// Packed dual-FP32 FMA (Blackwell)
__device__ __forceinline__ unsigned long long ffma2(unsigned long long a,
                                                    unsigned long long b,
                                                    unsigned long long c)
{
    unsigned long long d;
    asm("fma.rn.f32x2 %0, %1, %2, %3;" : "=l"(d) : "l"(a), "l"(b), "l"(c));
    return d;
}
__device__ __forceinline__ unsigned long long as_u64(double v)
{
    return __double_as_longlong(v);
}
__device__ __forceinline__ float hsum2(unsigned long long v)
{
    float lo, hi;
    asm("mov.b64 {%0, %1}, %2;" : "=f"(lo), "=f"(hi) : "l"(v));
    return lo + hi;
}

// Warp-autonomous: no smem, no barriers, no cp.async.
// Lane l (l < 25): patch q = l/5 within the warp's 5 patches, pixel row s = l%5.
// The 5 lanes sharing a patch issue identical coefficient/bias addresses ->
// warp-level broadcast: each patch's 240B is fetched from DRAM exactly once.
__global__ __launch_bounds__(NTHREADS, 5)
void ts_kernel(const float* __restrict__ pix,
               const float* __restrict__ coef,
               const float* __restrict__ bias,
               float* __restrict__ out)
{
    const int tid  = threadIdx.x;
    const int w    = tid >> 5;
    const int lane = tid & 31;
    if (lane >= 25) return;              // 25 active lanes per warp

    const int q = lane / 5;              // patch within warp (0..4)
    const int s = lane % 5;              // pixel row within patch (0..4)

    const int b   = blockIdx.x;          // 0..999
    const int pr  = b / 5;               // patch row 0..199
    const int cbp = (b - pr * 5) * 40 + w * 5 + q;   // patch col 0..199
    const int pg  = pr * PATCHES_PER_ROW + cbp;      // global patch id
    const int pixBase = (pr * PATCH + s) * IMG_W + cbp * PATCH;

    // Pixels: 5 contiguous (x,y) pairs = 5 LDG.64
    unsigned long long xy[PATCH];
    {
        const double* pp8 = (const double*)pix + pixBase;
        #pragma unroll
        for (int i = 0; i < PATCH; i++)
            xy[i] = as_u64(pp8[i]);
    }

    const float* cc0 = coef + (size_t)pg * COEF_PER_PATCH;   // 240B-aligned
    const float* bp  = bias + (size_t)pg * 3;
    float* o = out + pixBase;

    #pragma unroll
    for (int ch = 0; ch < 3; ch++) {
        // 5 LDG.128, each a 5-lane broadcast (16B-aligned: 240B patch, 80B channel)
        const double2* cp = (const double2*)(cc0 + ch * 20);
        double2 v0 = __ldg(cp + 0);
        double2 v1 = __ldg(cp + 1);
        double2 v2 = __ldg(cp + 2);
        double2 v3 = __ldg(cp + 3);
        double2 v4 = __ldg(cp + 4);
        const float bv = __ldg(bp + ch);

        unsigned long long acc[PATCH];
        {
            const unsigned long long c8 = as_u64(v4.x), c9 = as_u64(v4.y);
            #pragma unroll
            for (int i = 0; i < PATCH; i++)
                acc[i] = ffma2(c9, xy[i], c8);       // t=9 -> t=8
        }
        {
            const unsigned long long clo = as_u64(v3.x), chi = as_u64(v3.y);
            #pragma unroll
            for (int i = 0; i < PATCH; i++) acc[i] = ffma2(acc[i], xy[i], chi);
            #pragma unroll
            for (int i = 0; i < PATCH; i++) acc[i] = ffma2(acc[i], xy[i], clo);
        }
        {
            const unsigned long long clo = as_u64(v2.x), chi = as_u64(v2.y);
            #pragma unroll
            for (int i = 0; i < PATCH; i++) acc[i] = ffma2(acc[i], xy[i], chi);
            #pragma unroll
            for (int i = 0; i < PATCH; i++) acc[i] = ffma2(acc[i], xy[i], clo);
        }
        {
            const unsigned long long clo = as_u64(v1.x), chi = as_u64(v1.y);
            #pragma unroll
            for (int i = 0; i < PATCH; i++) acc[i] = ffma2(acc[i], xy[i], chi);
            #pragma unroll
            for (int i = 0; i < PATCH; i++) acc[i] = ffma2(acc[i], xy[i], clo);
        }
        {
            const unsigned long long clo = as_u64(v0.x), chi = as_u64(v0.y);
            #pragma unroll
            for (int i = 0; i < PATCH; i++) acc[i] = ffma2(acc[i], xy[i], chi);
            #pragma unroll
            for (int i = 0; i < PATCH; i++) acc[i] = ffma2(acc[i], xy[i], clo);
        }

        float* oc = o + ch * NUM_PIX;
        #pragma unroll
        for (int i = 0; i < PATCH; i++)
            oc[i] = hsum2(acc[i]) + bv;
    }
}

extern "C" void kernel_launch(void* const* d_in, const int* in_sizes, int n_in,
                              void* d_out, int out_size)
{
    const float* pix  = (const float*)d_in[0];   // [1000000, 2]
    const float* coef = (const float*)d_in[1];   // [40000, 3, 10, 2]
    const float* bias = (const float*)d_in[2];   // [40000, 3]
    float* out = (float*)d_out;                  // [3, 1000000]

    (void)in_sizes; (void)n_in; (void)out_size;
    ts_kernel<<<GRID, NTHREADS>>>(pix, coef, bias, out);
}

// round 12
// speedup vs baseline: 1.6031x; 1.6031x over previous
#include <cuda_runtime.h>
#include <cuda_pipeline_primitives.h>

// Problem constants (fixed by the reference):
//   image 1000x1000, patch 5x5 -> 200x200 = 40000 patches
//   coefficients [40000, 3, 10, 2], bias [40000, 3]
//   out [3, 1000000]
#define IMG_W           1000
#define NUM_PIX         1000000
#define PATCH           5
#define PATCHES_PER_ROW 200
#define COEF_PER_PATCH  60          // 3*10*2
#define PB              50          // patches per block (one quarter of a patch-row)
#define NTHREADS        320         // 300 compute threads (93.75% active)
#define GRID            800         // 200 patch-rows x 4 blocks

// Packed dual-FP32 FMA (Blackwell)
__device__ __forceinline__ unsigned long long ffma2(unsigned long long a,
                                                    unsigned long long b,
                                                    unsigned long long c)
{
    unsigned long long d;
    asm("fma.rn.f32x2 %0, %1, %2, %3;" : "=l"(d) : "l"(a), "l"(b), "l"(c));
    return d;
}
__device__ __forceinline__ unsigned long long as_u64(double v)
{
    return __double_as_longlong(v);
}
__device__ __forceinline__ float hsum2(unsigned long long v)
{
    float lo, hi;
    asm("mov.b64 {%0, %1}, %2;" : "=f"(lo), "=f"(hi) : "l"(v));
    return lo + hi;
}

__global__ __launch_bounds__(NTHREADS, 5)
void ts_kernel(const float* __restrict__ pix,
               const float* __restrict__ coef,
               const float* __restrict__ bias,
               float* __restrict__ out)
{
    __shared__ float sc[PB * COEF_PER_PATCH];   // 3000 floats, LINEAR (12000 B)
    __shared__ float sb[PB * 3 + 2];            // bias, 150 used

    const int tid = threadIdx.x;
    const int b   = blockIdx.x;          // 0..799
    const int pr  = b >> 2;              // patch row 0..199
    const int cb  = (b & 3) * PB;        // patch-col base: 0,50,100,150
    const int pbase   = pr * PATCHES_PER_ROW + cb;
    const int colBase = cb * PATCH;      // pixel column base: 0,250,500,750

    // ---- Coefficient + bias staging (cp.async; coeffs 16B, bias 8B granules) ----
    {
        // 50 patches * 15 float4 = 750 float4, contiguous (pbase*240B is 16B-aligned).
        const float4* g4 = (const float4*)(coef + (size_t)pbase * COEF_PER_PATCH);
        #pragma unroll
        for (int k = 0; k < 3; k++) {
            int idx = tid + k * NTHREADS;
            if (idx < 750)
                __pipeline_memcpy_async(&sc[idx * 4], &g4[idx], 16);
        }
        // Bias: 150 floats = 75 float2 (pbase*3*4B = 600B multiple -> 8B-aligned).
        if (tid < 75)
            __pipeline_memcpy_async(&sb[tid * 2],
                                    (const float2*)(bias + (size_t)pbase * 3) + tid, 8);
        __pipeline_commit();
    }

    // ---- Early pixel loads (independent of smem; overlap the coeff wait) ----
    const int p_local = tid % PB;        // 0..49
    const int seg     = tid / PB;        // 0..6 (only 0..4 compute)
    const int pixBase = (pr * PATCH + seg) * IMG_W + colBase + p_local * PATCH;

    unsigned long long xy[PATCH];
    if (tid < PB * PATCH) {
        const double* pp8 = (const double*)pix + pixBase;   // pixel n = double n
        #pragma unroll
        for (int i = 0; i < PATCH; i++)
            xy[i] = as_u64(pp8[i]);
    }

    __pipeline_wait_prior(0);
    __syncthreads();

    // ---- Compute + direct stores (300 threads; thread = 5-pixel segment) ----
    if (tid < PB * PATCH) {
        const float* cc0 = &sc[p_local * COEF_PER_PATCH];   // 240B stride: conflict-free LDS.128
        const float bv0 = sb[p_local * 3 + 0];
        const float bv1 = sb[p_local * 3 + 1];
        const float bv2 = sb[p_local * 3 + 2];
        float* o = out + pixBase;

        #pragma unroll
        for (int ch = 0; ch < 3; ch++) {
            const double2* cp = (const double2*)(cc0 + ch * 20);  // 16B-aligned
            const float bv = (ch == 0) ? bv0 : (ch == 1) ? bv1 : bv2;

            unsigned long long acc[PATCH];
            {
                double2 v = cp[4];                       // pairs t=8, t=9
                const unsigned long long c8 = as_u64(v.x), c9 = as_u64(v.y);
                #pragma unroll
                for (int i = 0; i < PATCH; i++)
                    acc[i] = ffma2(c9, xy[i], c8);
            }
            #pragma unroll
            for (int j = 3; j >= 0; j--) {
                double2 v = cp[j];                       // pairs t=2j, t=2j+1
                const unsigned long long clo = as_u64(v.x), chi = as_u64(v.y);
                #pragma unroll
                for (int i = 0; i < PATCH; i++)
                    acc[i] = ffma2(acc[i], xy[i], chi);
                #pragma unroll
                for (int i = 0; i < PATCH; i++)
                    acc[i] = ffma2(acc[i], xy[i], clo);
            }
            float* oc = o + ch * NUM_PIX;
            #pragma unroll
            for (int i = 0; i < PATCH; i++)
                oc[i] = hsum2(acc[i]) + bv;              // warp run: contiguous stores
        }
    }
}

extern "C" void kernel_launch(void* const* d_in, const int* in_sizes, int n_in,
                              void* d_out, int out_size)
{
    const float* pix  = (const float*)d_in[0];   // [1000000, 2]
    const float* coef = (const float*)d_in[1];   // [40000, 3, 10, 2]
    const float* bias = (const float*)d_in[2];   // [40000, 3]
    float* out = (float*)d_out;                  // [3, 1000000]

    (void)in_sizes; (void)n_in; (void)out_size;
    ts_kernel<<<GRID, NTHREADS>>>(pix, coef, bias, out);
}